// round 1
// baseline (speedup 1.0000x reference)
#include <cuda_runtime.h>
#include <math.h>

#define IN_DIM 128
#define HID 256
#define EMB 128
#define MAXN 50000
#define MAXE 800000

// ---------------- scratch (device globals; no allocation) ----------------
__device__ float d_deg[MAXN];
__device__ float d_dinv[MAXN];
__device__ float d_h1[MAXN * HID];    // x @ W1
__device__ float d_agg1[MAXN * HID];  // scatter accum -> relu'd layer-1 output (in place)
__device__ float d_h2[MAXN * EMB];    // out1 @ W2 (pre-aggregation)
__device__ float d_agg2[MAXN * EMB];  // scatter accum -> final H (in place)
__device__ float d_gsum[EMB];

// ---------------- helpers ----------------
__device__ __forceinline__ void red_add_v4(float* p, float4 v) {
    asm volatile("red.global.add.v4.f32 [%0], {%1,%2,%3,%4};"
                 :: "l"(p), "f"(v.x), "f"(v.y), "f"(v.z), "f"(v.w) : "memory");
}

__device__ __forceinline__ float warp_sum(float v) {
    #pragma unroll
    for (int o = 16; o; o >>= 1) v += __shfl_down_sync(0xffffffffu, v, o);
    return v;
}

// ---------------- init: zero accumulators ----------------
__global__ void k_init(int n) {
    int i = blockIdx.x * blockDim.x + threadIdx.x;
    int stride = gridDim.x * blockDim.x;
    float4 z = make_float4(0.f, 0.f, 0.f, 0.f);
    float4* a1 = (float4*)d_agg1; int n1 = n * (HID / 4);
    float4* a2 = (float4*)d_agg2; int n2 = n * (EMB / 4);
    for (int t = i; t < n1; t += stride) a1[t] = z;
    for (int t = i; t < n2; t += stride) a2[t] = z;
    for (int t = i; t < n; t += stride) d_deg[t] = 0.f;
    if (i < EMB) d_gsum[i] = 0.f;
}

// ---------------- degree + inverse-sqrt ----------------
__global__ void k_deg(const int* __restrict__ dst, int E) {
    int i = blockIdx.x * blockDim.x + threadIdx.x;
    if (i < E) atomicAdd(&d_deg[dst[i]], 1.0f);
}

__global__ void k_dinv(int n) {
    int i = blockIdx.x * blockDim.x + threadIdx.x;
    if (i < n) d_dinv[i] = rsqrtf(d_deg[i] + 1.0f);
}

// ---------------- tiled SGEMM: C[M,N] = A[M,K] @ B[K,N] ----------------
// BM=64 BN=64 BK=16, 256 threads, 4x4 per thread. K multiple of 16, N multiple of 64.
__global__ void sgemm64(int M, int N, int K,
                        const float* __restrict__ A,
                        const float* __restrict__ B,
                        float* __restrict__ C) {
    __shared__ float As[16][64 + 4];
    __shared__ float Bs[16][64];
    int t = threadIdx.x;
    int row0 = blockIdx.y * 64;
    int col0 = blockIdx.x * 64;

    int arow = t >> 2;          // 0..63
    int acol = (t & 3) << 2;    // 0,4,8,12
    int brow = t >> 4;          // 0..15
    int bcol = (t & 15) << 2;   // 0..60
    int tx = t & 15, ty = t >> 4;

    float acc[4][4];
    #pragma unroll
    for (int i = 0; i < 4; i++)
        #pragma unroll
        for (int j = 0; j < 4; j++) acc[i][j] = 0.f;

    for (int k0 = 0; k0 < K; k0 += 16) {
        float4 av = make_float4(0.f, 0.f, 0.f, 0.f);
        int gr = row0 + arow;
        if (gr < M) av = *(const float4*)(A + (size_t)gr * K + k0 + acol);
        As[acol + 0][arow] = av.x;
        As[acol + 1][arow] = av.y;
        As[acol + 2][arow] = av.z;
        As[acol + 3][arow] = av.w;

        float4 bv = *(const float4*)(B + (size_t)(k0 + brow) * N + col0 + bcol);
        *(float4*)&Bs[brow][bcol] = bv;
        __syncthreads();

        #pragma unroll
        for (int k = 0; k < 16; k++) {
            float4 ra = *(const float4*)&As[k][ty * 4];
            float4 rb = *(const float4*)&Bs[k][tx * 4];
            acc[0][0] += ra.x * rb.x; acc[0][1] += ra.x * rb.y; acc[0][2] += ra.x * rb.z; acc[0][3] += ra.x * rb.w;
            acc[1][0] += ra.y * rb.x; acc[1][1] += ra.y * rb.y; acc[1][2] += ra.y * rb.z; acc[1][3] += ra.y * rb.w;
            acc[2][0] += ra.z * rb.x; acc[2][1] += ra.z * rb.y; acc[2][2] += ra.z * rb.z; acc[2][3] += ra.z * rb.w;
            acc[3][0] += ra.w * rb.x; acc[3][1] += ra.w * rb.y; acc[3][2] += ra.w * rb.z; acc[3][3] += ra.w * rb.w;
        }
        __syncthreads();
    }

    #pragma unroll
    for (int i = 0; i < 4; i++) {
        int gr = row0 + ty * 4 + i;
        if (gr < M) {
            float4 o = make_float4(acc[i][0], acc[i][1], acc[i][2], acc[i][3]);
            *(float4*)(C + (size_t)gr * N + col0 + tx * 4) = o;
        }
    }
}

// ---------------- edge scatter: AGG[dst] += H[src] * (dinv[src]*dinv[dst]) ----------------
template <int NCOL4>  // columns/4 per row
__global__ void k_scatter(const int* __restrict__ src, const int* __restrict__ dst,
                          const float* __restrict__ H, float* __restrict__ AGG, int E) {
    int warp = (blockIdx.x * blockDim.x + threadIdx.x) >> 5;
    int lane = threadIdx.x & 31;
    if (warp >= E) return;
    int s = src[warp], d = dst[warp];
    float nrm = d_dinv[s] * d_dinv[d];
    const float4* hs = (const float4*)(H + (size_t)s * (NCOL4 * 4));
    float* ag = AGG + (size_t)d * (NCOL4 * 4);
    #pragma unroll
    for (int j = lane; j < NCOL4; j += 32) {
        float4 v = hs[j];
        v.x *= nrm; v.y *= nrm; v.z *= nrm; v.w *= nrm;
        red_add_v4(ag + j * 4, v);
    }
}

// ---------------- self-loop + bias + relu (in place on AGG) ----------------
template <int NCOL>
__global__ void k_self(const float* __restrict__ H, float* __restrict__ AGG,
                       const float* __restrict__ bias, int n) {
    int idx = blockIdx.x * blockDim.x + threadIdx.x;
    int total = n * (NCOL / 4);
    if (idx >= total) return;
    int row = idx / (NCOL / 4);
    int c4 = idx - row * (NCOL / 4);
    float di = d_dinv[row];
    float d2 = di * di;
    float4 h = ((const float4*)(H + (size_t)row * NCOL))[c4];
    float4 a = ((const float4*)(AGG + (size_t)row * NCOL))[c4];
    float4 b = ((const float4*)bias)[c4];
    float4 o;
    o.x = fmaxf(a.x + h.x * d2 + b.x, 0.f);
    o.y = fmaxf(a.y + h.y * d2 + b.y, 0.f);
    o.z = fmaxf(a.z + h.z * d2 + b.z, 0.f);
    o.w = fmaxf(a.w + h.w * d2 + b.w, 0.f);
    ((float4*)(AGG + (size_t)row * NCOL))[c4] = o;
}

// ---------------- column mean partial sums ----------------
__global__ void k_colmean(const float* __restrict__ H, int n) {
    int col = threadIdx.x & (EMB - 1);
    int half = threadIdx.x >> 7;  // 0/1 (256 threads, 128 cols)
    float acc = 0.f;
    for (int r = blockIdx.x * 2 + half; r < n; r += gridDim.x * 2)
        acc += H[(size_t)r * EMB + col];
    atomicAdd(&d_gsum[col], acc);
}

// ---------------- global heads: value + global_logits (1 block, 256 threads) ----------------
__global__ void k_head(const float* __restrict__ fc1W, const float* __restrict__ fc1b,
                       const float* __restrict__ fc2W, const float* __restrict__ fc2b,
                       const float* __restrict__ gpW, const float* __restrict__ gpb,
                       float* __restrict__ out_global, float* __restrict__ out_value,
                       float invN) {
    __shared__ float g[EMB];
    __shared__ float red[256];
    int t = threadIdx.x;
    if (t < EMB) g[t] = d_gsum[t] * invN;
    __syncthreads();
    // v[t] = relu(g @ fc1W[:,t] + fc1b[t]), t in [0,256)
    float acc = fc1b[t];
    #pragma unroll 4
    for (int k = 0; k < EMB; k++) acc += g[k] * fc1W[k * HID + t];
    float v = fmaxf(acc, 0.f);
    // value = v @ fc2W + fc2b
    red[t] = v * fc2W[t];
    __syncthreads();
    for (int o = 128; o; o >>= 1) {
        if (t < o) red[t] += red[t + o];
        __syncthreads();
    }
    if (t == 0) out_value[0] = red[0] + fc2b[0];
    __syncthreads();
    // global_logits = g @ gpW + gpb
    red[t] = (t < EMB) ? g[t] * gpW[t] : 0.f;
    __syncthreads();
    for (int o = 128; o; o >>= 1) {
        if (t < o) red[t] += red[t + o];
        __syncthreads();
    }
    if (t == 0) out_global[0] = red[0] + gpb[0];
}

// ---------------- node logits: warp per row, H[EMB] @ npW[EMB,3] ----------------
__global__ void k_nodelogits(const float* __restrict__ H, const float* __restrict__ npW,
                             const float* __restrict__ npb, float* __restrict__ out, int n) {
    int warp = (blockIdx.x * blockDim.x + threadIdx.x) >> 5;
    int lane = threadIdx.x & 31;
    if (warp >= n) return;
    float4 hv = ((const float4*)(H + (size_t)warp * EMB))[lane];
    int k = lane * 4;
    float a0 = hv.x * npW[(k + 0) * 3 + 0] + hv.y * npW[(k + 1) * 3 + 0] +
               hv.z * npW[(k + 2) * 3 + 0] + hv.w * npW[(k + 3) * 3 + 0];
    float a1 = hv.x * npW[(k + 0) * 3 + 1] + hv.y * npW[(k + 1) * 3 + 1] +
               hv.z * npW[(k + 2) * 3 + 1] + hv.w * npW[(k + 3) * 3 + 1];
    float a2 = hv.x * npW[(k + 0) * 3 + 2] + hv.y * npW[(k + 1) * 3 + 2] +
               hv.z * npW[(k + 2) * 3 + 2] + hv.w * npW[(k + 3) * 3 + 2];
    a0 = warp_sum(a0); a1 = warp_sum(a1); a2 = warp_sum(a2);
    if (lane == 0) {
        out[(size_t)warp * 3 + 0] = a0 + npb[0];
        out[(size_t)warp * 3 + 1] = a1 + npb[1];
        out[(size_t)warp * 3 + 2] = a2 + npb[2];
    }
}

// ---------------- edge logits: warp per edge ----------------
__global__ void k_edgelogits(const int* __restrict__ src, const int* __restrict__ dst,
                             const float* __restrict__ H, const float* __restrict__ epW,
                             const float* __restrict__ epb, float* __restrict__ out, int E) {
    __shared__ float sW[2 * EMB * 2];  // [256][2]
    for (int i = threadIdx.x; i < 2 * EMB * 2; i += blockDim.x) sW[i] = epW[i];
    __syncthreads();
    int warp = (blockIdx.x * blockDim.x + threadIdx.x) >> 5;
    int lane = threadIdx.x & 31;
    if (warp >= E) return;
    int s = src[warp], d = dst[warp];
    float4 hs = ((const float4*)(H + (size_t)s * EMB))[lane];
    float4 hd = ((const float4*)(H + (size_t)d * EMB))[lane];
    int k = lane * 4;
    float a0, a1;
    a0  = hs.x * sW[(k + 0) * 2 + 0] + hs.y * sW[(k + 1) * 2 + 0]
        + hs.z * sW[(k + 2) * 2 + 0] + hs.w * sW[(k + 3) * 2 + 0];
    a1  = hs.x * sW[(k + 0) * 2 + 1] + hs.y * sW[(k + 1) * 2 + 1]
        + hs.z * sW[(k + 2) * 2 + 1] + hs.w * sW[(k + 3) * 2 + 1];
    int kd = EMB + k;
    a0 += hd.x * sW[(kd + 0) * 2 + 0] + hd.y * sW[(kd + 1) * 2 + 0]
        + hd.z * sW[(kd + 2) * 2 + 0] + hd.w * sW[(kd + 3) * 2 + 0];
    a1 += hd.x * sW[(kd + 0) * 2 + 1] + hd.y * sW[(kd + 1) * 2 + 1]
        + hd.z * sW[(kd + 2) * 2 + 1] + hd.w * sW[(kd + 3) * 2 + 1];
    a0 = warp_sum(a0); a1 = warp_sum(a1);
    if (lane == 0) {
        out[(size_t)warp * 2 + 0] = a0 + epb[0];
        out[(size_t)warp * 2 + 1] = a1 + epb[1];
    }
}

// ---------------- launch ----------------
extern "C" void kernel_launch(void* const* d_in, const int* in_sizes, int n_in,
                              void* d_out, int out_size) {
    const float* x     = (const float*)d_in[0];
    const int*   ei    = (const int*)d_in[1];
    const float* W1    = (const float*)d_in[2];
    const float* b1    = (const float*)d_in[3];
    const float* W2    = (const float*)d_in[4];
    const float* b2    = (const float*)d_in[5];
    const float* fc1W  = (const float*)d_in[6];
    const float* fc1b  = (const float*)d_in[7];
    const float* fc2W  = (const float*)d_in[8];
    const float* fc2b  = (const float*)d_in[9];
    const float* npW   = (const float*)d_in[10];
    const float* npb   = (const float*)d_in[11];
    const float* epW   = (const float*)d_in[12];
    const float* epb   = (const float*)d_in[13];
    const float* gpW   = (const float*)d_in[14];
    const float* gpb   = (const float*)d_in[15];

    int n = in_sizes[0] / IN_DIM;   // 50000
    int E = in_sizes[1] / 2;        // 800000
    const int* src = ei;
    const int* dst = ei + E;

    float* out = (float*)d_out;
    float* out_node   = out;                       // n*3
    float* out_edge   = out + (size_t)n * 3;       // E*2
    float* out_global = out + (size_t)n * 3 + (size_t)E * 2;
    float* out_value  = out_global + 1;

    float *h1, *agg1, *h2, *agg2;
    cudaGetSymbolAddress((void**)&h1, d_h1);
    cudaGetSymbolAddress((void**)&agg1, d_agg1);
    cudaGetSymbolAddress((void**)&h2, d_h2);
    cudaGetSymbolAddress((void**)&agg2, d_agg2);

    // 1) zero accumulators + degree
    k_init<<<1024, 256>>>(n);
    // 2) degrees, dinv
    k_deg<<<(E + 255) / 256, 256>>>(dst, E);
    k_dinv<<<(n + 255) / 256, 256>>>(n);
    // 3) h1 = x @ W1   [n,128]@[128,256]
    {
        dim3 grid(HID / 64, (n + 63) / 64);
        sgemm64<<<grid, 256>>>(n, HID, IN_DIM, x, W1, h1);
    }
    // 4) scatter layer 1 (HID cols -> 64 float4)
    k_scatter<HID / 4><<<(E + 7) / 8, 256>>>(src, dst, h1, agg1, E);
    // 5) self-loop + bias + relu -> agg1 holds layer-1 output
    k_self<HID><<<((size_t)n * (HID / 4) + 255) / 256, 256>>>(h1, agg1, b1, n);
    // 6) h2 = out1 @ W2   [n,256]@[256,128]
    {
        dim3 grid(EMB / 64, (n + 63) / 64);
        sgemm64<<<grid, 256>>>(n, EMB, HID, agg1, W2, h2);
    }
    // 7) scatter layer 2 (EMB cols -> 32 float4)
    k_scatter<EMB / 4><<<(E + 7) / 8, 256>>>(src, dst, h2, agg2, E);
    // 8) self-loop + bias + relu -> agg2 holds final H
    k_self<EMB><<<((size_t)n * (EMB / 4) + 255) / 256, 256>>>(h2, agg2, b2, n);
    // 9) column sums for mean
    k_colmean<<<256, 256>>>(agg2, n);
    // 10) value + global heads
    k_head<<<1, 256>>>(fc1W, fc1b, fc2W, fc2b, gpW, gpb, out_global, out_value, 1.0f / (float)n);
    // 11) node logits
    k_nodelogits<<<(n + 7) / 8, 256>>>(agg2, npW, npb, out_node, n);
    // 12) edge logits
    k_edgelogits<<<(E + 7) / 8, 256>>>(src, dst, agg2, epW, epb, out_edge, E);
}

// round 2
// speedup vs baseline: 1.5821x; 1.5821x over previous
#include <cuda_runtime.h>
#include <math.h>

#define IN_DIM 128
#define HID 256
#define EMB 128
#define MAXN 50000
#define MAXE 800000

// ---------------- scratch (device globals; no allocation) ----------------
__device__ float d_deg[MAXN];
__device__ float d_dinv[MAXN];
__device__ float d_aggx[MAXN * IN_DIM];  // self-init x*d2, then += scatter(x)
__device__ float d_h1[MAXN * HID];       // relu(aggx@W1 + b1)
__device__ float d_h2[MAXN * EMB];       // h1 @ W2 (raw)
__device__ float d_agg2[MAXN * EMB];     // init h2*d2, then += scatter(h2), then relu(+b2)
__device__ float d_gsum[EMB];
__device__ float4 d_pnode[MAXN];         // [pu0, pu1, pv0, pv1]

// ---------------- helpers ----------------
__device__ __forceinline__ void red_add_v4(float* p, float4 v) {
    asm volatile("red.global.add.v4.f32 [%0], {%1,%2,%3,%4};"
                 :: "l"(p), "f"(v.x), "f"(v.y), "f"(v.z), "f"(v.w) : "memory");
}

__device__ __forceinline__ float warp_sum(float v) {
    #pragma unroll
    for (int o = 16; o; o >>= 1) v += __shfl_down_sync(0xffffffffu, v, o);
    return v;
}

// ---------------- zero deg + gsum ----------------
__global__ void k_zero(int n) {
    int i = blockIdx.x * blockDim.x + threadIdx.x;
    int stride = gridDim.x * blockDim.x;
    for (int t = i; t < n; t += stride) d_deg[t] = 0.f;
    if (i < EMB) d_gsum[i] = 0.f;
}

__global__ void k_deg(const int* __restrict__ dst, int E) {
    int i = blockIdx.x * blockDim.x + threadIdx.x;
    if (i < E) atomicAdd(&d_deg[dst[i]], 1.0f);
}

__global__ void k_dinv(int n) {
    int i = blockIdx.x * blockDim.x + threadIdx.x;
    if (i < n) d_dinv[i] = rsqrtf(d_deg[i] + 1.0f);
}

// ---------------- aggx = x * dinv^2 (self-loop pre-init) ----------------
__global__ void k_initx(const float* __restrict__ x, int n) {
    int idx = blockIdx.x * blockDim.x + threadIdx.x;
    int total = n * (IN_DIM / 4);
    if (idx >= total) return;
    int row = idx >> 5;          // IN_DIM/4 == 32
    int c4 = idx & 31;
    float di = d_dinv[row];
    float d2 = di * di;
    float4 v = ((const float4*)x)[(size_t)row * 32 + c4];
    v.x *= d2; v.y *= d2; v.z *= d2; v.w *= d2;
    ((float4*)d_aggx)[(size_t)row * 32 + c4] = v;
}

// ---------------- edge scatter: AGG[dst] += H[src] * (dinv[src]*dinv[dst]) ----------------
// NCOL = 128: warp per edge, one float4 per lane.
__global__ void k_scatter128(const int* __restrict__ src, const int* __restrict__ dst,
                             const float* __restrict__ H, float* __restrict__ AGG, int E) {
    int warp = (blockIdx.x * blockDim.x + threadIdx.x) >> 5;
    int lane = threadIdx.x & 31;
    if (warp >= E) return;
    int s = src[warp], d = dst[warp];
    float nrm = d_dinv[s] * d_dinv[d];
    float4 v = ((const float4*)(H + (size_t)s * EMB))[lane];
    v.x *= nrm; v.y *= nrm; v.z *= nrm; v.w *= nrm;
    red_add_v4(AGG + (size_t)d * EMB + lane * 4, v);
}

// ---------------- tiled SGEMM: 128x128 tile, BK=16, 256 threads, 8x8/thread ----
// MODE 0: C = relu(acc + bias)          (bias per col)
// MODE 1: C = acc (raw); C2 = acc * dinv[row]^2
template <int MODE>
__global__ __launch_bounds__(256, 2)
void sgemm128(int M, int N, int K,
              const float* __restrict__ A, const float* __restrict__ B,
              const float* __restrict__ bias,
              float* __restrict__ C, float* __restrict__ C2) {
    __shared__ float As[16][128];
    __shared__ float Bs[16][128];
    int t = threadIdx.x;
    int row0 = blockIdx.y * 128, col0 = blockIdx.x * 128;
    int ar = t >> 1, ac = (t & 1) * 8;
    int br = t >> 4, bc = (t & 15) * 8;
    int ty = t >> 4, tx = t & 15;

    float acc[8][8];
    #pragma unroll
    for (int i = 0; i < 8; i++)
        #pragma unroll
        for (int j = 0; j < 8; j++) acc[i][j] = 0.f;

    for (int k0 = 0; k0 < K; k0 += 16) {
        int gr = row0 + ar;
        float4 a0 = make_float4(0.f, 0.f, 0.f, 0.f);
        float4 a1 = make_float4(0.f, 0.f, 0.f, 0.f);
        if (gr < M) {
            a0 = *(const float4*)(A + (size_t)gr * K + k0 + ac);
            a1 = *(const float4*)(A + (size_t)gr * K + k0 + ac + 4);
        }
        As[ac + 0][ar] = a0.x; As[ac + 1][ar] = a0.y;
        As[ac + 2][ar] = a0.z; As[ac + 3][ar] = a0.w;
        As[ac + 4][ar] = a1.x; As[ac + 5][ar] = a1.y;
        As[ac + 6][ar] = a1.z; As[ac + 7][ar] = a1.w;

        *(float4*)&Bs[br][bc]     = *(const float4*)(B + (size_t)(k0 + br) * N + col0 + bc);
        *(float4*)&Bs[br][bc + 4] = *(const float4*)(B + (size_t)(k0 + br) * N + col0 + bc + 4);
        __syncthreads();

        #pragma unroll
        for (int k = 0; k < 16; k++) {
            float4 ra0 = *(const float4*)&As[k][ty * 8];
            float4 ra1 = *(const float4*)&As[k][ty * 8 + 4];
            float4 rb0 = *(const float4*)&Bs[k][tx * 8];
            float4 rb1 = *(const float4*)&Bs[k][tx * 8 + 4];
            float a[8] = {ra0.x, ra0.y, ra0.z, ra0.w, ra1.x, ra1.y, ra1.z, ra1.w};
            float b[8] = {rb0.x, rb0.y, rb0.z, rb0.w, rb1.x, rb1.y, rb1.z, rb1.w};
            #pragma unroll
            for (int i = 0; i < 8; i++)
                #pragma unroll
                for (int j = 0; j < 8; j++)
                    acc[i][j] += a[i] * b[j];
        }
        __syncthreads();
    }

    if (MODE == 0) {
        float4 bv0 = *(const float4*)(bias + col0 + tx * 8);
        float4 bv1 = *(const float4*)(bias + col0 + tx * 8 + 4);
        float bb[8] = {bv0.x, bv0.y, bv0.z, bv0.w, bv1.x, bv1.y, bv1.z, bv1.w};
        #pragma unroll
        for (int i = 0; i < 8; i++) {
            int gr = row0 + ty * 8 + i;
            if (gr < M) {
                float4 o0, o1;
                o0.x = fmaxf(acc[i][0] + bb[0], 0.f); o0.y = fmaxf(acc[i][1] + bb[1], 0.f);
                o0.z = fmaxf(acc[i][2] + bb[2], 0.f); o0.w = fmaxf(acc[i][3] + bb[3], 0.f);
                o1.x = fmaxf(acc[i][4] + bb[4], 0.f); o1.y = fmaxf(acc[i][5] + bb[5], 0.f);
                o1.z = fmaxf(acc[i][6] + bb[6], 0.f); o1.w = fmaxf(acc[i][7] + bb[7], 0.f);
                *(float4*)(C + (size_t)gr * N + col0 + tx * 8)     = o0;
                *(float4*)(C + (size_t)gr * N + col0 + tx * 8 + 4) = o1;
            }
        }
    } else {
        #pragma unroll
        for (int i = 0; i < 8; i++) {
            int gr = row0 + ty * 8 + i;
            if (gr < M) {
                float di = d_dinv[gr];
                float d2 = di * di;
                float4 r0 = make_float4(acc[i][0], acc[i][1], acc[i][2], acc[i][3]);
                float4 r1 = make_float4(acc[i][4], acc[i][5], acc[i][6], acc[i][7]);
                *(float4*)(C + (size_t)gr * N + col0 + tx * 8)     = r0;
                *(float4*)(C + (size_t)gr * N + col0 + tx * 8 + 4) = r1;
                float4 s0 = make_float4(r0.x * d2, r0.y * d2, r0.z * d2, r0.w * d2);
                float4 s1 = make_float4(r1.x * d2, r1.y * d2, r1.z * d2, r1.w * d2);
                *(float4*)(C2 + (size_t)gr * N + col0 + tx * 8)     = s0;
                *(float4*)(C2 + (size_t)gr * N + col0 + tx * 8 + 4) = s1;
            }
        }
    }
}

// ---------------- final relu(+bias) on agg2 + column sums for mean ----------------
__global__ void k_relu2_mean(float* __restrict__ AGG, const float* __restrict__ bias, int n) {
    int c4 = threadIdx.x & 31;   // float4 column index (128 cols)
    int ry = threadIdx.x >> 5;   // 0..7
    float4 b = ((const float4*)bias)[c4];
    float4 sum = make_float4(0.f, 0.f, 0.f, 0.f);
    for (int row = blockIdx.x * 8 + ry; row < n; row += gridDim.x * 8) {
        float4 a = ((float4*)AGG)[(size_t)row * 32 + c4];
        a.x = fmaxf(a.x + b.x, 0.f);
        a.y = fmaxf(a.y + b.y, 0.f);
        a.z = fmaxf(a.z + b.z, 0.f);
        a.w = fmaxf(a.w + b.w, 0.f);
        ((float4*)AGG)[(size_t)row * 32 + c4] = a;
        sum.x += a.x; sum.y += a.y; sum.z += a.z; sum.w += a.w;
    }
    __shared__ float4 sm[256];
    sm[threadIdx.x] = sum;
    __syncthreads();
    if (ry == 0) {
        #pragma unroll
        for (int i = 1; i < 8; i++) {
            float4 o = sm[i * 32 + c4];
            sum.x += o.x; sum.y += o.y; sum.z += o.z; sum.w += o.w;
        }
        atomicAdd(&d_gsum[c4 * 4 + 0], sum.x);
        atomicAdd(&d_gsum[c4 * 4 + 1], sum.y);
        atomicAdd(&d_gsum[c4 * 4 + 2], sum.z);
        atomicAdd(&d_gsum[c4 * 4 + 3], sum.w);
    }
}

// ---------------- global heads: value + global_logits ----------------
__global__ void k_head(const float* __restrict__ fc1W, const float* __restrict__ fc1b,
                       const float* __restrict__ fc2W, const float* __restrict__ fc2b,
                       const float* __restrict__ gpW, const float* __restrict__ gpb,
                       float* __restrict__ out_global, float* __restrict__ out_value,
                       float invN) {
    __shared__ float g[EMB];
    __shared__ float red[256];
    int t = threadIdx.x;
    if (t < EMB) g[t] = d_gsum[t] * invN;
    __syncthreads();
    float acc = fc1b[t];
    #pragma unroll 4
    for (int k = 0; k < EMB; k++) acc += g[k] * fc1W[k * HID + t];
    float v = fmaxf(acc, 0.f);
    red[t] = v * fc2W[t];
    __syncthreads();
    for (int o = 128; o; o >>= 1) {
        if (t < o) red[t] += red[t + o];
        __syncthreads();
    }
    if (t == 0) out_value[0] = red[0] + fc2b[0];
    __syncthreads();
    red[t] = (t < EMB) ? g[t] * gpW[t] : 0.f;
    __syncthreads();
    for (int o = 128; o; o >>= 1) {
        if (t < o) red[t] += red[t + o];
        __syncthreads();
    }
    if (t == 0) out_global[0] = red[0] + gpb[0];
}

// ---------------- per-node heads: node logits + edge-projection P ----------------
// out_node[row] = H[row] @ npW + npb (3)
// pnode[row]    = (H[row] @ epW[0:128], H[row] @ epW[128:256])  (4 floats)
__global__ void k_pernode(const float* __restrict__ H,
                          const float* __restrict__ npW, const float* __restrict__ npb,
                          const float* __restrict__ epW,
                          float* __restrict__ out_node, int n) {
    __shared__ float sNp[EMB * 3];      // 384
    __shared__ float sEu[EMB * 2];      // epW rows 0..127
    __shared__ float sEv[EMB * 2];      // epW rows 128..255
    for (int i = threadIdx.x; i < EMB * 3; i += blockDim.x) sNp[i] = npW[i];
    for (int i = threadIdx.x; i < EMB * 2; i += blockDim.x) sEu[i] = epW[i];
    for (int i = threadIdx.x; i < EMB * 2; i += blockDim.x) sEv[i] = epW[EMB * 2 + i];
    __syncthreads();

    int warp = (blockIdx.x * blockDim.x + threadIdx.x) >> 5;
    int lane = threadIdx.x & 31;
    if (warp >= n) return;
    float4 h = ((const float4*)(H + (size_t)warp * EMB))[lane];
    float hv[4] = {h.x, h.y, h.z, h.w};
    int k = lane * 4;
    float np0 = 0.f, np1 = 0.f, np2 = 0.f;
    float pu0 = 0.f, pu1 = 0.f, pv0 = 0.f, pv1 = 0.f;
    #pragma unroll
    for (int j = 0; j < 4; j++) {
        float x = hv[j];
        np0 += x * sNp[(k + j) * 3 + 0];
        np1 += x * sNp[(k + j) * 3 + 1];
        np2 += x * sNp[(k + j) * 3 + 2];
        pu0 += x * sEu[(k + j) * 2 + 0];
        pu1 += x * sEu[(k + j) * 2 + 1];
        pv0 += x * sEv[(k + j) * 2 + 0];
        pv1 += x * sEv[(k + j) * 2 + 1];
    }
    np0 = warp_sum(np0); np1 = warp_sum(np1); np2 = warp_sum(np2);
    pu0 = warp_sum(pu0); pu1 = warp_sum(pu1);
    pv0 = warp_sum(pv0); pv1 = warp_sum(pv1);
    if (lane == 0) {
        out_node[(size_t)warp * 3 + 0] = np0 + npb[0];
        out_node[(size_t)warp * 3 + 1] = np1 + npb[1];
        out_node[(size_t)warp * 3 + 2] = np2 + npb[2];
        d_pnode[warp] = make_float4(pu0, pu1, pv0, pv1);
    }
}

// ---------------- edge logits from precomputed projections ----------------
__global__ void k_edge(const int* __restrict__ src, const int* __restrict__ dst,
                       const float* __restrict__ epb, float* __restrict__ out, int E) {
    int i = blockIdx.x * blockDim.x + threadIdx.x;
    if (i >= E) return;
    int s = src[i], d = dst[i];
    float4 ps = d_pnode[s];
    float4 pd = d_pnode[d];
    float2 o;
    o.x = ps.x + pd.z + epb[0];
    o.y = ps.y + pd.w + epb[1];
    *(float2*)(out + (size_t)i * 2) = o;
}

// ---------------- launch ----------------
extern "C" void kernel_launch(void* const* d_in, const int* in_sizes, int n_in,
                              void* d_out, int out_size) {
    const float* x     = (const float*)d_in[0];
    const int*   ei    = (const int*)d_in[1];
    const float* W1    = (const float*)d_in[2];
    const float* b1    = (const float*)d_in[3];
    const float* W2    = (const float*)d_in[4];
    const float* b2    = (const float*)d_in[5];
    const float* fc1W  = (const float*)d_in[6];
    const float* fc1b  = (const float*)d_in[7];
    const float* fc2W  = (const float*)d_in[8];
    const float* fc2b  = (const float*)d_in[9];
    const float* npW   = (const float*)d_in[10];
    const float* npb   = (const float*)d_in[11];
    const float* epW   = (const float*)d_in[12];
    const float* epb   = (const float*)d_in[13];
    const float* gpW   = (const float*)d_in[14];
    const float* gpb   = (const float*)d_in[15];

    int n = in_sizes[0] / IN_DIM;   // 50000
    int E = in_sizes[1] / 2;        // 800000
    const int* src = ei;
    const int* dst = ei + E;

    float* out = (float*)d_out;
    float* out_node   = out;
    float* out_edge   = out + (size_t)n * 3;
    float* out_global = out + (size_t)n * 3 + (size_t)E * 2;
    float* out_value  = out_global + 1;

    float *aggx, *h1, *h2, *agg2;
    cudaGetSymbolAddress((void**)&aggx, d_aggx);
    cudaGetSymbolAddress((void**)&h1, d_h1);
    cudaGetSymbolAddress((void**)&h2, d_h2);
    cudaGetSymbolAddress((void**)&agg2, d_agg2);

    // 1) zero deg + gsum
    k_zero<<<256, 256>>>(n);
    // 2) degree + dinv
    k_deg<<<(E + 255) / 256, 256>>>(dst, E);
    k_dinv<<<(n + 255) / 256, 256>>>(n);
    // 3) aggx = x * d2 (self-loop init)
    k_initx<<<((size_t)n * 32 + 255) / 256, 256>>>(x, n);
    // 4) aggx += scatter(x)   (linearity: aggregate BEFORE W1)
    k_scatter128<<<(E + 7) / 8, 256>>>(src, dst, x, aggx, E);
    // 5) h1 = relu(aggx @ W1 + b1)   [n,128]@[128,256]
    {
        dim3 grid(HID / 128, (n + 127) / 128);
        sgemm128<0><<<grid, 256>>>(n, HID, IN_DIM, aggx, W1, b1, h1, nullptr);
    }
    // 6) h2 = h1 @ W2 (raw) ; agg2 = h2 * d2   [n,256]@[256,128]
    {
        dim3 grid(EMB / 128, (n + 127) / 128);
        sgemm128<1><<<grid, 256>>>(n, EMB, HID, h1, W2, nullptr, h2, agg2);
    }
    // 7) agg2 += scatter(h2)
    k_scatter128<<<(E + 7) / 8, 256>>>(src, dst, h2, agg2, E);
    // 8) agg2 = relu(agg2 + b2), accumulate column sums
    k_relu2_mean<<<256, 256>>>(agg2, b2, n);
    // 9) value + global heads
    k_head<<<1, 256>>>(fc1W, fc1b, fc2W, fc2b, gpW, gpb, out_global, out_value, 1.0f / (float)n);
    // 10) node logits + edge projections
    k_pernode<<<(n + 7) / 8, 256>>>(agg2, npW, npb, epW, out_node, n);
    // 11) edge logits
    k_edge<<<(E + 255) / 256, 256>>>(src, dst, epb, out_edge, E);
}

// round 3
// speedup vs baseline: 1.9268x; 1.2178x over previous
#include <cuda_runtime.h>
#include <math.h>

#define IN_DIM 128
#define HID 256
#define EMB 128
#define MAXN 50000
#define MAXE 800000
#define SCAN_BS 256

// ---------------- scratch (device globals; no allocation) ----------------
__device__ int   d_degi[MAXN];
__device__ float d_dinv[MAXN];
__device__ int   d_off[MAXN + 1];
__device__ int   d_cursor[MAXN];
__device__ int   d_partial[(MAXN + SCAN_BS - 1) / SCAN_BS + 1];   // 196
__device__ int   d_elist[MAXE];
__device__ float d_aggx[MAXN * IN_DIM];
__device__ float d_h1[MAXN * HID];
__device__ float d_h2[MAXN * EMB];
__device__ float d_agg2[MAXN * EMB];
__device__ float d_gsum[EMB];
__device__ float4 d_pnode[MAXN];

__device__ __forceinline__ float warp_sum(float v) {
    #pragma unroll
    for (int o = 16; o; o >>= 1) v += __shfl_down_sync(0xffffffffu, v, o);
    return v;
}

// ---------------- zero deg + gsum ----------------
__global__ void k_zero(int n) {
    int i = blockIdx.x * blockDim.x + threadIdx.x;
    int stride = gridDim.x * blockDim.x;
    for (int t = i; t < n; t += stride) d_degi[t] = 0;
    if (i < EMB) d_gsum[i] = 0.f;
}

__global__ void k_deg(const int* __restrict__ dst, int E) {
    int i = blockIdx.x * blockDim.x + threadIdx.x;
    if (i < E) atomicAdd(&d_degi[dst[i]], 1);
}

__global__ void k_dinv(int n) {
    int i = blockIdx.x * blockDim.x + threadIdx.x;
    if (i < n) d_dinv[i] = rsqrtf((float)d_degi[i] + 1.0f);
}

// ---------------- 3-kernel exclusive scan of d_degi -> d_off ----------------
__global__ void k_scan1(int n) {
    __shared__ int sm[SCAN_BS];
    int t = threadIdx.x;
    int i = blockIdx.x * SCAN_BS + t;
    int v = (i < n) ? d_degi[i] : 0;
    sm[t] = v;
    __syncthreads();
    // Hillis-Steele inclusive scan
    #pragma unroll
    for (int o = 1; o < SCAN_BS; o <<= 1) {
        int add = (t >= o) ? sm[t - o] : 0;
        __syncthreads();
        sm[t] += add;
        __syncthreads();
    }
    if (i < n) d_off[i] = sm[t] - v;  // exclusive within chunk
    if (t == SCAN_BS - 1) d_partial[blockIdx.x] = sm[t];
}

__global__ void k_scan2(int nblk) {
    __shared__ int sm[SCAN_BS];
    int t = threadIdx.x;
    int v = (t < nblk) ? d_partial[t] : 0;
    sm[t] = v;
    __syncthreads();
    #pragma unroll
    for (int o = 1; o < SCAN_BS; o <<= 1) {
        int add = (t >= o) ? sm[t - o] : 0;
        __syncthreads();
        sm[t] += add;
        __syncthreads();
    }
    if (t < nblk) d_partial[t] = sm[t] - v;  // exclusive
}

__global__ void k_scan3(int n, int E) {
    int i = blockIdx.x * blockDim.x + threadIdx.x;
    if (i < n) {
        int o = d_off[i] + d_partial[i / SCAN_BS];
        d_off[i] = o;
        d_cursor[i] = o;
    }
    if (i == 0) d_off[n] = E;
}

// ---------------- bucket fill: CSR edge list by dst ----------------
__global__ void k_fill(const int* __restrict__ src, const int* __restrict__ dst, int E) {
    int i = blockIdx.x * blockDim.x + threadIdx.x;
    if (i >= E) return;
    int d = dst[i];
    int pos = atomicAdd(&d_cursor[d], 1);
    d_elist[pos] = src[i];
}

// ---------------- gather-aggregate: warp per node ----------------
// OUT[v] = H[v]*dinv[v]^2 + sum_{e in CSR[v]} H[src_e] * dinv[src_e]*dinv[v]
// RELU: additionally +bias then relu.
template <int NC4, bool RELU>
__global__ void k_gather(const float* __restrict__ H, float* __restrict__ OUT,
                         const float* __restrict__ bias, int n) {
    int warp = (blockIdx.x * blockDim.x + threadIdx.x) >> 5;
    int lane = threadIdx.x & 31;
    if (warp >= n) return;
    float dv = d_dinv[warp];
    float d2 = dv * dv;
    const float4* Hv = (const float4*)H;
    float4 h = Hv[(size_t)warp * NC4 + lane];
    float4 acc = make_float4(h.x * d2, h.y * d2, h.z * d2, h.w * d2);
    int e = d_off[warp], end = d_off[warp + 1];
    int s_next = (e < end) ? d_elist[e] : 0;
    for (; e < end; e++) {
        int s = s_next;
        s_next = (e + 1 < end) ? d_elist[e + 1] : 0;
        float nrm = d_dinv[s] * dv;
        float4 v = Hv[(size_t)s * NC4 + lane];
        acc.x += v.x * nrm; acc.y += v.y * nrm;
        acc.z += v.z * nrm; acc.w += v.w * nrm;
    }
    if (RELU) {
        float4 b = ((const float4*)bias)[lane];
        acc.x = fmaxf(acc.x + b.x, 0.f);
        acc.y = fmaxf(acc.y + b.y, 0.f);
        acc.z = fmaxf(acc.z + b.z, 0.f);
        acc.w = fmaxf(acc.w + b.w, 0.f);
    }
    ((float4*)OUT)[(size_t)warp * NC4 + lane] = acc;
}

// ---------------- tiled SGEMM: 128x128 tile, BK=16, 256 threads, 8x8/thread ----
// MODE 0: C = relu(acc + bias); MODE 1: C = acc (raw)
template <int MODE>
__global__ __launch_bounds__(256, 2)
void sgemm128(int M, int N, int K,
              const float* __restrict__ A, const float* __restrict__ B,
              const float* __restrict__ bias, float* __restrict__ C) {
    __shared__ float As[16][128];
    __shared__ float Bs[16][128];
    int t = threadIdx.x;
    int row0 = blockIdx.y * 128, col0 = blockIdx.x * 128;
    int ar = t >> 1, ac = (t & 1) * 8;
    int br = t >> 4, bc = (t & 15) * 8;
    int ty = t >> 4, tx = t & 15;

    float acc[8][8];
    #pragma unroll
    for (int i = 0; i < 8; i++)
        #pragma unroll
        for (int j = 0; j < 8; j++) acc[i][j] = 0.f;

    for (int k0 = 0; k0 < K; k0 += 16) {
        int gr = row0 + ar;
        float4 a0 = make_float4(0.f, 0.f, 0.f, 0.f);
        float4 a1 = make_float4(0.f, 0.f, 0.f, 0.f);
        if (gr < M) {
            a0 = *(const float4*)(A + (size_t)gr * K + k0 + ac);
            a1 = *(const float4*)(A + (size_t)gr * K + k0 + ac + 4);
        }
        As[ac + 0][ar] = a0.x; As[ac + 1][ar] = a0.y;
        As[ac + 2][ar] = a0.z; As[ac + 3][ar] = a0.w;
        As[ac + 4][ar] = a1.x; As[ac + 5][ar] = a1.y;
        As[ac + 6][ar] = a1.z; As[ac + 7][ar] = a1.w;

        *(float4*)&Bs[br][bc]     = *(const float4*)(B + (size_t)(k0 + br) * N + col0 + bc);
        *(float4*)&Bs[br][bc + 4] = *(const float4*)(B + (size_t)(k0 + br) * N + col0 + bc + 4);
        __syncthreads();

        #pragma unroll
        for (int k = 0; k < 16; k++) {
            float4 ra0 = *(const float4*)&As[k][ty * 8];
            float4 ra1 = *(const float4*)&As[k][ty * 8 + 4];
            float4 rb0 = *(const float4*)&Bs[k][tx * 8];
            float4 rb1 = *(const float4*)&Bs[k][tx * 8 + 4];
            float a[8] = {ra0.x, ra0.y, ra0.z, ra0.w, ra1.x, ra1.y, ra1.z, ra1.w};
            float b[8] = {rb0.x, rb0.y, rb0.z, rb0.w, rb1.x, rb1.y, rb1.z, rb1.w};
            #pragma unroll
            for (int i = 0; i < 8; i++)
                #pragma unroll
                for (int j = 0; j < 8; j++)
                    acc[i][j] += a[i] * b[j];
        }
        __syncthreads();
    }

    if (MODE == 0) {
        float4 bv0 = *(const float4*)(bias + col0 + tx * 8);
        float4 bv1 = *(const float4*)(bias + col0 + tx * 8 + 4);
        float bb[8] = {bv0.x, bv0.y, bv0.z, bv0.w, bv1.x, bv1.y, bv1.z, bv1.w};
        #pragma unroll
        for (int i = 0; i < 8; i++) {
            int gr = row0 + ty * 8 + i;
            if (gr < M) {
                float4 o0, o1;
                o0.x = fmaxf(acc[i][0] + bb[0], 0.f); o0.y = fmaxf(acc[i][1] + bb[1], 0.f);
                o0.z = fmaxf(acc[i][2] + bb[2], 0.f); o0.w = fmaxf(acc[i][3] + bb[3], 0.f);
                o1.x = fmaxf(acc[i][4] + bb[4], 0.f); o1.y = fmaxf(acc[i][5] + bb[5], 0.f);
                o1.z = fmaxf(acc[i][6] + bb[6], 0.f); o1.w = fmaxf(acc[i][7] + bb[7], 0.f);
                *(float4*)(C + (size_t)gr * N + col0 + tx * 8)     = o0;
                *(float4*)(C + (size_t)gr * N + col0 + tx * 8 + 4) = o1;
            }
        }
    } else {
        #pragma unroll
        for (int i = 0; i < 8; i++) {
            int gr = row0 + ty * 8 + i;
            if (gr < M) {
                *(float4*)(C + (size_t)gr * N + col0 + tx * 8) =
                    make_float4(acc[i][0], acc[i][1], acc[i][2], acc[i][3]);
                *(float4*)(C + (size_t)gr * N + col0 + tx * 8 + 4) =
                    make_float4(acc[i][4], acc[i][5], acc[i][6], acc[i][7]);
            }
        }
    }
}

// ---------------- column sums of H (read-only) ----------------
__global__ void k_colmean(const float* __restrict__ H, int n) {
    int c4 = threadIdx.x & 31;
    int ry = threadIdx.x >> 5;
    float4 sum = make_float4(0.f, 0.f, 0.f, 0.f);
    for (int row = blockIdx.x * 8 + ry; row < n; row += gridDim.x * 8) {
        float4 a = ((const float4*)H)[(size_t)row * 32 + c4];
        sum.x += a.x; sum.y += a.y; sum.z += a.z; sum.w += a.w;
    }
    __shared__ float4 sm[256];
    sm[threadIdx.x] = sum;
    __syncthreads();
    if (ry == 0) {
        #pragma unroll
        for (int i = 1; i < 8; i++) {
            float4 o = sm[i * 32 + c4];
            sum.x += o.x; sum.y += o.y; sum.z += o.z; sum.w += o.w;
        }
        atomicAdd(&d_gsum[c4 * 4 + 0], sum.x);
        atomicAdd(&d_gsum[c4 * 4 + 1], sum.y);
        atomicAdd(&d_gsum[c4 * 4 + 2], sum.z);
        atomicAdd(&d_gsum[c4 * 4 + 3], sum.w);
    }
}

// ---------------- global heads ----------------
__global__ void k_head(const float* __restrict__ fc1W, const float* __restrict__ fc1b,
                       const float* __restrict__ fc2W, const float* __restrict__ fc2b,
                       const float* __restrict__ gpW, const float* __restrict__ gpb,
                       float* __restrict__ out_global, float* __restrict__ out_value,
                       float invN) {
    __shared__ float g[EMB];
    __shared__ float red[256];
    int t = threadIdx.x;
    if (t < EMB) g[t] = d_gsum[t] * invN;
    __syncthreads();
    float acc = fc1b[t];
    #pragma unroll 4
    for (int k = 0; k < EMB; k++) acc += g[k] * fc1W[k * HID + t];
    float v = fmaxf(acc, 0.f);
    red[t] = v * fc2W[t];
    __syncthreads();
    for (int o = 128; o; o >>= 1) {
        if (t < o) red[t] += red[t + o];
        __syncthreads();
    }
    if (t == 0) out_value[0] = red[0] + fc2b[0];
    __syncthreads();
    red[t] = (t < EMB) ? g[t] * gpW[t] : 0.f;
    __syncthreads();
    for (int o = 128; o; o >>= 1) {
        if (t < o) red[t] += red[t + o];
        __syncthreads();
    }
    if (t == 0) out_global[0] = red[0] + gpb[0];
}

// ---------------- per-node heads: node logits + edge projections ----------------
__global__ void k_pernode(const float* __restrict__ H,
                          const float* __restrict__ npW, const float* __restrict__ npb,
                          const float* __restrict__ epW,
                          float* __restrict__ out_node, int n) {
    __shared__ float sNp[EMB * 3];
    __shared__ float sEu[EMB * 2];
    __shared__ float sEv[EMB * 2];
    for (int i = threadIdx.x; i < EMB * 3; i += blockDim.x) sNp[i] = npW[i];
    for (int i = threadIdx.x; i < EMB * 2; i += blockDim.x) sEu[i] = epW[i];
    for (int i = threadIdx.x; i < EMB * 2; i += blockDim.x) sEv[i] = epW[EMB * 2 + i];
    __syncthreads();

    int warp = (blockIdx.x * blockDim.x + threadIdx.x) >> 5;
    int lane = threadIdx.x & 31;
    if (warp >= n) return;
    float4 h = ((const float4*)(H + (size_t)warp * EMB))[lane];
    float hv[4] = {h.x, h.y, h.z, h.w};
    int k = lane * 4;
    float np0 = 0.f, np1 = 0.f, np2 = 0.f;
    float pu0 = 0.f, pu1 = 0.f, pv0 = 0.f, pv1 = 0.f;
    #pragma unroll
    for (int j = 0; j < 4; j++) {
        float x = hv[j];
        np0 += x * sNp[(k + j) * 3 + 0];
        np1 += x * sNp[(k + j) * 3 + 1];
        np2 += x * sNp[(k + j) * 3 + 2];
        pu0 += x * sEu[(k + j) * 2 + 0];
        pu1 += x * sEu[(k + j) * 2 + 1];
        pv0 += x * sEv[(k + j) * 2 + 0];
        pv1 += x * sEv[(k + j) * 2 + 1];
    }
    np0 = warp_sum(np0); np1 = warp_sum(np1); np2 = warp_sum(np2);
    pu0 = warp_sum(pu0); pu1 = warp_sum(pu1);
    pv0 = warp_sum(pv0); pv1 = warp_sum(pv1);
    if (lane == 0) {
        out_node[(size_t)warp * 3 + 0] = np0 + npb[0];
        out_node[(size_t)warp * 3 + 1] = np1 + npb[1];
        out_node[(size_t)warp * 3 + 2] = np2 + npb[2];
        d_pnode[warp] = make_float4(pu0, pu1, pv0, pv1);
    }
}

// ---------------- edge logits from precomputed projections ----------------
__global__ void k_edge(const int* __restrict__ src, const int* __restrict__ dst,
                       const float* __restrict__ epb, float* __restrict__ out, int E) {
    int i = blockIdx.x * blockDim.x + threadIdx.x;
    if (i >= E) return;
    int s = src[i], d = dst[i];
    float4 ps = d_pnode[s];
    float4 pd = d_pnode[d];
    float2 o;
    o.x = ps.x + pd.z + epb[0];
    o.y = ps.y + pd.w + epb[1];
    *(float2*)(out + (size_t)i * 2) = o;
}

// ---------------- launch ----------------
extern "C" void kernel_launch(void* const* d_in, const int* in_sizes, int n_in,
                              void* d_out, int out_size) {
    const float* x     = (const float*)d_in[0];
    const int*   ei    = (const int*)d_in[1];
    const float* W1    = (const float*)d_in[2];
    const float* b1    = (const float*)d_in[3];
    const float* W2    = (const float*)d_in[4];
    const float* b2    = (const float*)d_in[5];
    const float* fc1W  = (const float*)d_in[6];
    const float* fc1b  = (const float*)d_in[7];
    const float* fc2W  = (const float*)d_in[8];
    const float* fc2b  = (const float*)d_in[9];
    const float* npW   = (const float*)d_in[10];
    const float* npb   = (const float*)d_in[11];
    const float* epW   = (const float*)d_in[12];
    const float* epb   = (const float*)d_in[13];
    const float* gpW   = (const float*)d_in[14];
    const float* gpb   = (const float*)d_in[15];

    int n = in_sizes[0] / IN_DIM;   // 50000
    int E = in_sizes[1] / 2;        // 800000
    const int* src = ei;
    const int* dst = ei + E;

    float* out = (float*)d_out;
    float* out_node   = out;
    float* out_edge   = out + (size_t)n * 3;
    float* out_global = out + (size_t)n * 3 + (size_t)E * 2;
    float* out_value  = out_global + 1;

    float *aggx, *h1, *h2, *agg2;
    cudaGetSymbolAddress((void**)&aggx, d_aggx);
    cudaGetSymbolAddress((void**)&h1, d_h1);
    cudaGetSymbolAddress((void**)&h2, d_h2);
    cudaGetSymbolAddress((void**)&agg2, d_agg2);

    int nblk = (n + SCAN_BS - 1) / SCAN_BS;   // 196

    // CSR build
    k_zero<<<256, 256>>>(n);
    k_deg<<<(E + 255) / 256, 256>>>(dst, E);
    k_dinv<<<(n + 255) / 256, 256>>>(n);
    k_scan1<<<nblk, SCAN_BS>>>(n);
    k_scan2<<<1, SCAN_BS>>>(nblk);
    k_scan3<<<(n + 255) / 256, 256>>>(n, E);
    k_fill<<<(E + 255) / 256, 256>>>(src, dst, E);

    // Layer 1: aggregate x, then GEMM (+bias+relu)
    k_gather<IN_DIM / 4, false><<<(n + 7) / 8, 256>>>(x, aggx, nullptr, n);
    {
        dim3 grid(HID / 128, (n + 127) / 128);
        sgemm128<0><<<grid, 256>>>(n, HID, IN_DIM, aggx, W1, b1, h1);
    }
    // Layer 2: GEMM (raw), aggregate h2 (+bias+relu fused)
    {
        dim3 grid(EMB / 128, (n + 127) / 128);
        sgemm128<1><<<grid, 256>>>(n, EMB, HID, h1, W2, nullptr, h2);
    }
    k_gather<EMB / 4, true><<<(n + 7) / 8, 256>>>(h2, agg2, b2, n);

    // Heads
    k_colmean<<<256, 256>>>(agg2, n);
    k_head<<<1, 256>>>(fc1W, fc1b, fc2W, fc2b, gpW, gpb, out_global, out_value, 1.0f / (float)n);
    k_pernode<<<(n + 7) / 8, 256>>>(agg2, npW, npb, epW, out_node, n);
    k_edge<<<(E + 255) / 256, 256>>>(src, dst, epb, out_edge, E);
}

// round 4
// speedup vs baseline: 2.8403x; 1.4741x over previous
#include <cuda_runtime.h>
#include <math.h>
#include <stdint.h>

#define IN_DIM 128
#define HID 256
#define EMB 128
#define MAXN 50000
#define MAXE 800000
#define SCAN_BS 256

// ---------------- scratch (device globals; no allocation) ----------------
__device__ int   d_degi[MAXN];
__device__ float d_dinv[MAXN];
__device__ int   d_off[MAXN + 1];
__device__ int   d_cursor[MAXN];
__device__ int   d_partial[(MAXN + SCAN_BS - 1) / SCAN_BS + 1];
__device__ int   d_elist[MAXE];
__device__ float d_aggx[MAXN * IN_DIM];
__device__ float d_h1[MAXN * HID];
__device__ float d_h2[MAXN * EMB];
__device__ float d_agg2[MAXN * EMB];
__device__ float d_gsum[EMB];
__device__ float4 d_pnode[MAXN];

__device__ __forceinline__ float warp_sum(float v) {
    #pragma unroll
    for (int o = 16; o; o >>= 1) v += __shfl_down_sync(0xffffffffu, v, o);
    return v;
}

__device__ __forceinline__ uint32_t f2tf32(float f) {
    uint32_t r;
    asm("cvt.rna.tf32.f32 %0, %1;" : "=r"(r) : "f"(f));
    return r;
}

// ---------------- zero deg + gsum ----------------
__global__ void k_zero(int n) {
    int i = blockIdx.x * blockDim.x + threadIdx.x;
    int stride = gridDim.x * blockDim.x;
    for (int t = i; t < n; t += stride) d_degi[t] = 0;
    if (i < EMB) d_gsum[i] = 0.f;
}

__global__ void k_deg(const int* __restrict__ dst, int E) {
    int i = blockIdx.x * blockDim.x + threadIdx.x;
    if (i < E) atomicAdd(&d_degi[dst[i]], 1);
}

__global__ void k_dinv(int n) {
    int i = blockIdx.x * blockDim.x + threadIdx.x;
    if (i < n) d_dinv[i] = rsqrtf((float)d_degi[i] + 1.0f);
}

// ---------------- 3-kernel exclusive scan ----------------
__global__ void k_scan1(int n) {
    __shared__ int sm[SCAN_BS];
    int t = threadIdx.x;
    int i = blockIdx.x * SCAN_BS + t;
    int v = (i < n) ? d_degi[i] : 0;
    sm[t] = v;
    __syncthreads();
    #pragma unroll
    for (int o = 1; o < SCAN_BS; o <<= 1) {
        int add = (t >= o) ? sm[t - o] : 0;
        __syncthreads();
        sm[t] += add;
        __syncthreads();
    }
    if (i < n) d_off[i] = sm[t] - v;
    if (t == SCAN_BS - 1) d_partial[blockIdx.x] = sm[t];
}

__global__ void k_scan2(int nblk) {
    __shared__ int sm[SCAN_BS];
    int t = threadIdx.x;
    int v = (t < nblk) ? d_partial[t] : 0;
    sm[t] = v;
    __syncthreads();
    #pragma unroll
    for (int o = 1; o < SCAN_BS; o <<= 1) {
        int add = (t >= o) ? sm[t - o] : 0;
        __syncthreads();
        sm[t] += add;
        __syncthreads();
    }
    if (t < nblk) d_partial[t] = sm[t] - v;
}

__global__ void k_scan3(int n, int E) {
    int i = blockIdx.x * blockDim.x + threadIdx.x;
    if (i < n) {
        int o = d_off[i] + d_partial[i / SCAN_BS];
        d_off[i] = o;
        d_cursor[i] = o;
    }
    if (i == 0) d_off[n] = E;
}

__global__ void k_fill(const int* __restrict__ src, const int* __restrict__ dst, int E) {
    int i = blockIdx.x * blockDim.x + threadIdx.x;
    if (i >= E) return;
    int d = dst[i];
    int pos = atomicAdd(&d_cursor[d], 1);
    d_elist[pos] = src[i];
}

// ---------------- gather-aggregate: warp per node ----------------
template <int NC4, bool RELU>
__global__ void k_gather(const float* __restrict__ H, float* __restrict__ OUT,
                         const float* __restrict__ bias, int n) {
    int warp = (blockIdx.x * blockDim.x + threadIdx.x) >> 5;
    int lane = threadIdx.x & 31;
    if (warp >= n) return;
    float dv = d_dinv[warp];
    float d2 = dv * dv;
    const float4* Hv = (const float4*)H;
    float4 h = Hv[(size_t)warp * NC4 + lane];
    float4 acc = make_float4(h.x * d2, h.y * d2, h.z * d2, h.w * d2);
    int e = d_off[warp], end = d_off[warp + 1];
    int s_next = (e < end) ? d_elist[e] : 0;
    for (; e < end; e++) {
        int s = s_next;
        s_next = (e + 1 < end) ? d_elist[e + 1] : 0;
        float nrm = d_dinv[s] * dv;
        float4 v = Hv[(size_t)s * NC4 + lane];
        acc.x += v.x * nrm; acc.y += v.y * nrm;
        acc.z += v.z * nrm; acc.w += v.w * nrm;
    }
    if (RELU) {
        float4 b = ((const float4*)bias)[lane];
        acc.x = fmaxf(acc.x + b.x, 0.f);
        acc.y = fmaxf(acc.y + b.y, 0.f);
        acc.z = fmaxf(acc.z + b.z, 0.f);
        acc.w = fmaxf(acc.w + b.w, 0.f);
    }
    ((float4*)OUT)[(size_t)warp * NC4 + lane] = acc;
}

// ---------------- tf32 tensor-core GEMM: 128x128 tile, BK=32, 256 threads ----
// 8 warps in 2x4 grid, warp tile 64x32, mma.sync.m16n8k8.tf32.
// MODE 0: C = relu(acc + bias); MODE 1: C = acc (raw)
#define APAD 36
#define BPAD 136
template <int MODE>
__global__ __launch_bounds__(256, 2)
void tgemm128(int M, int N, int K,
              const float* __restrict__ A, const float* __restrict__ B,
              const float* __restrict__ bias, float* __restrict__ C) {
    __shared__ uint32_t As[128][APAD];   // [m][k], tf32 bits
    __shared__ uint32_t Bs[32][BPAD];    // [k][n], tf32 bits

    int t = threadIdx.x;
    int lane = t & 31;
    int warp = t >> 5;
    int wr = warp >> 2;       // 0..1  (64-row band)
    int wc = warp & 3;        // 0..3  (32-col band)
    int row0 = blockIdx.y * 128, col0 = blockIdx.x * 128;

    float acc[4][4][4];
    #pragma unroll
    for (int i = 0; i < 4; i++)
        #pragma unroll
        for (int j = 0; j < 4; j++)
            #pragma unroll
            for (int r = 0; r < 4; r++) acc[i][j][r] = 0.f;

    int arow = t >> 1;              // 0..127
    int acb = (t & 1) * 16;         // 0 or 16
    int brow = t >> 3;              // 0..31
    int bcb = (t & 7) * 16;         // 0..112

    for (int k0 = 0; k0 < K; k0 += 32) {
        // load A 128x32 -> As (tf32 converted)
        {
            int gr = row0 + arow;
            const float* ap = A + (size_t)gr * K + k0 + acb;
            #pragma unroll
            for (int i = 0; i < 4; i++) {
                float4 v = make_float4(0.f, 0.f, 0.f, 0.f);
                if (gr < M) v = *(const float4*)(ap + i * 4);
                uint4 u;
                u.x = f2tf32(v.x); u.y = f2tf32(v.y);
                u.z = f2tf32(v.z); u.w = f2tf32(v.w);
                *(uint4*)&As[arow][acb + i * 4] = u;
            }
        }
        // load B 32x128 -> Bs (tf32 converted)
        {
            const float* bp = B + (size_t)(k0 + brow) * N + col0 + bcb;
            #pragma unroll
            for (int i = 0; i < 4; i++) {
                float4 v = *(const float4*)(bp + i * 4);
                uint4 u;
                u.x = f2tf32(v.x); u.y = f2tf32(v.y);
                u.z = f2tf32(v.z); u.w = f2tf32(v.w);
                *(uint4*)&Bs[brow][bcb + i * 4] = u;
            }
        }
        __syncthreads();

        #pragma unroll
        for (int ks = 0; ks < 4; ks++) {
            int kk = ks * 8;
            uint32_t af[4][4];
            #pragma unroll
            for (int mi = 0; mi < 4; mi++) {
                int mr = wr * 64 + mi * 16 + (lane >> 2);
                int kc = kk + (lane & 3);
                af[mi][0] = As[mr][kc];
                af[mi][1] = As[mr + 8][kc];
                af[mi][2] = As[mr][kc + 4];
                af[mi][3] = As[mr + 8][kc + 4];
            }
            uint32_t bf[4][2];
            #pragma unroll
            for (int nj = 0; nj < 4; nj++) {
                int bc = wc * 32 + nj * 8 + (lane >> 2);
                int kr = kk + (lane & 3);
                bf[nj][0] = Bs[kr][bc];
                bf[nj][1] = Bs[kr + 4][bc];
            }
            #pragma unroll
            for (int mi = 0; mi < 4; mi++)
                #pragma unroll
                for (int nj = 0; nj < 4; nj++) {
                    asm volatile(
                        "mma.sync.aligned.m16n8k8.row.col.f32.tf32.tf32.f32 "
                        "{%0,%1,%2,%3}, {%4,%5,%6,%7}, {%8,%9}, {%0,%1,%2,%3};"
                        : "+f"(acc[mi][nj][0]), "+f"(acc[mi][nj][1]),
                          "+f"(acc[mi][nj][2]), "+f"(acc[mi][nj][3])
                        : "r"(af[mi][0]), "r"(af[mi][1]), "r"(af[mi][2]), "r"(af[mi][3]),
                          "r"(bf[nj][0]), "r"(bf[nj][1]));
                }
        }
        __syncthreads();
    }

    // epilogue
    #pragma unroll
    for (int mi = 0; mi < 4; mi++) {
        int r_lo = row0 + wr * 64 + mi * 16 + (lane >> 2);
        int r_hi = r_lo + 8;
        #pragma unroll
        for (int nj = 0; nj < 4; nj++) {
            int c = col0 + wc * 32 + nj * 8 + (lane & 3) * 2;
            float b0 = 0.f, b1 = 0.f;
            if (MODE == 0) { b0 = bias[c]; b1 = bias[c + 1]; }
            float2 lo, hi;
            if (MODE == 0) {
                lo.x = fmaxf(acc[mi][nj][0] + b0, 0.f);
                lo.y = fmaxf(acc[mi][nj][1] + b1, 0.f);
                hi.x = fmaxf(acc[mi][nj][2] + b0, 0.f);
                hi.y = fmaxf(acc[mi][nj][3] + b1, 0.f);
            } else {
                lo.x = acc[mi][nj][0]; lo.y = acc[mi][nj][1];
                hi.x = acc[mi][nj][2]; hi.y = acc[mi][nj][3];
            }
            if (r_lo < M) *(float2*)(C + (size_t)r_lo * N + c) = lo;
            if (r_hi < M) *(float2*)(C + (size_t)r_hi * N + c) = hi;
        }
    }
}

// ---------------- column sums of H (read-only) ----------------
__global__ void k_colmean(const float* __restrict__ H, int n) {
    int c4 = threadIdx.x & 31;
    int ry = threadIdx.x >> 5;
    float4 sum = make_float4(0.f, 0.f, 0.f, 0.f);
    for (int row = blockIdx.x * 8 + ry; row < n; row += gridDim.x * 8) {
        float4 a = ((const float4*)H)[(size_t)row * 32 + c4];
        sum.x += a.x; sum.y += a.y; sum.z += a.z; sum.w += a.w;
    }
    __shared__ float4 sm[256];
    sm[threadIdx.x] = sum;
    __syncthreads();
    if (ry == 0) {
        #pragma unroll
        for (int i = 1; i < 8; i++) {
            float4 o = sm[i * 32 + c4];
            sum.x += o.x; sum.y += o.y; sum.z += o.z; sum.w += o.w;
        }
        atomicAdd(&d_gsum[c4 * 4 + 0], sum.x);
        atomicAdd(&d_gsum[c4 * 4 + 1], sum.y);
        atomicAdd(&d_gsum[c4 * 4 + 2], sum.z);
        atomicAdd(&d_gsum[c4 * 4 + 3], sum.w);
    }
}

// ---------------- global heads ----------------
__global__ void k_head(const float* __restrict__ fc1W, const float* __restrict__ fc1b,
                       const float* __restrict__ fc2W, const float* __restrict__ fc2b,
                       const float* __restrict__ gpW, const float* __restrict__ gpb,
                       float* __restrict__ out_global, float* __restrict__ out_value,
                       float invN) {
    __shared__ float g[EMB];
    __shared__ float red[256];
    int t = threadIdx.x;
    if (t < EMB) g[t] = d_gsum[t] * invN;
    __syncthreads();
    float acc = fc1b[t];
    #pragma unroll 4
    for (int k = 0; k < EMB; k++) acc += g[k] * fc1W[k * HID + t];
    float v = fmaxf(acc, 0.f);
    red[t] = v * fc2W[t];
    __syncthreads();
    for (int o = 128; o; o >>= 1) {
        if (t < o) red[t] += red[t + o];
        __syncthreads();
    }
    if (t == 0) out_value[0] = red[0] + fc2b[0];
    __syncthreads();
    red[t] = (t < EMB) ? g[t] * gpW[t] : 0.f;
    __syncthreads();
    for (int o = 128; o; o >>= 1) {
        if (t < o) red[t] += red[t + o];
        __syncthreads();
    }
    if (t == 0) out_global[0] = red[0] + gpb[0];
}

// ---------------- per-node heads: node logits + edge projections ----------------
__global__ void k_pernode(const float* __restrict__ H,
                          const float* __restrict__ npW, const float* __restrict__ npb,
                          const float* __restrict__ epW,
                          float* __restrict__ out_node, int n) {
    __shared__ float sNp[EMB * 3];
    __shared__ float sEu[EMB * 2];
    __shared__ float sEv[EMB * 2];
    for (int i = threadIdx.x; i < EMB * 3; i += blockDim.x) sNp[i] = npW[i];
    for (int i = threadIdx.x; i < EMB * 2; i += blockDim.x) sEu[i] = epW[i];
    for (int i = threadIdx.x; i < EMB * 2; i += blockDim.x) sEv[i] = epW[EMB * 2 + i];
    __syncthreads();

    int warp = (blockIdx.x * blockDim.x + threadIdx.x) >> 5;
    int lane = threadIdx.x & 31;
    if (warp >= n) return;
    float4 h = ((const float4*)(H + (size_t)warp * EMB))[lane];
    float hv[4] = {h.x, h.y, h.z, h.w};
    int k = lane * 4;
    float np0 = 0.f, np1 = 0.f, np2 = 0.f;
    float pu0 = 0.f, pu1 = 0.f, pv0 = 0.f, pv1 = 0.f;
    #pragma unroll
    for (int j = 0; j < 4; j++) {
        float x = hv[j];
        np0 += x * sNp[(k + j) * 3 + 0];
        np1 += x * sNp[(k + j) * 3 + 1];
        np2 += x * sNp[(k + j) * 3 + 2];
        pu0 += x * sEu[(k + j) * 2 + 0];
        pu1 += x * sEu[(k + j) * 2 + 1];
        pv0 += x * sEv[(k + j) * 2 + 0];
        pv1 += x * sEv[(k + j) * 2 + 1];
    }
    np0 = warp_sum(np0); np1 = warp_sum(np1); np2 = warp_sum(np2);
    pu0 = warp_sum(pu0); pu1 = warp_sum(pu1);
    pv0 = warp_sum(pv0); pv1 = warp_sum(pv1);
    if (lane == 0) {
        out_node[(size_t)warp * 3 + 0] = np0 + npb[0];
        out_node[(size_t)warp * 3 + 1] = np1 + npb[1];
        out_node[(size_t)warp * 3 + 2] = np2 + npb[2];
        d_pnode[warp] = make_float4(pu0, pu1, pv0, pv1);
    }
}

// ---------------- edge logits ----------------
__global__ void k_edge(const int* __restrict__ src, const int* __restrict__ dst,
                       const float* __restrict__ epb, float* __restrict__ out, int E) {
    int i = blockIdx.x * blockDim.x + threadIdx.x;
    if (i >= E) return;
    int s = src[i], d = dst[i];
    float4 ps = d_pnode[s];
    float4 pd = d_pnode[d];
    float2 o;
    o.x = ps.x + pd.z + epb[0];
    o.y = ps.y + pd.w + epb[1];
    *(float2*)(out + (size_t)i * 2) = o;
}

// ---------------- launch ----------------
extern "C" void kernel_launch(void* const* d_in, const int* in_sizes, int n_in,
                              void* d_out, int out_size) {
    const float* x     = (const float*)d_in[0];
    const int*   ei    = (const int*)d_in[1];
    const float* W1    = (const float*)d_in[2];
    const float* b1    = (const float*)d_in[3];
    const float* W2    = (const float*)d_in[4];
    const float* b2    = (const float*)d_in[5];
    const float* fc1W  = (const float*)d_in[6];
    const float* fc1b  = (const float*)d_in[7];
    const float* fc2W  = (const float*)d_in[8];
    const float* fc2b  = (const float*)d_in[9];
    const float* npW   = (const float*)d_in[10];
    const float* npb   = (const float*)d_in[11];
    const float* epW   = (const float*)d_in[12];
    const float* epb   = (const float*)d_in[13];
    const float* gpW   = (const float*)d_in[14];
    const float* gpb   = (const float*)d_in[15];

    int n = in_sizes[0] / IN_DIM;   // 50000
    int E = in_sizes[1] / 2;        // 800000
    const int* src = ei;
    const int* dst = ei + E;

    float* out = (float*)d_out;
    float* out_node   = out;
    float* out_edge   = out + (size_t)n * 3;
    float* out_global = out + (size_t)n * 3 + (size_t)E * 2;
    float* out_value  = out_global + 1;

    float *aggx, *h1, *h2, *agg2;
    cudaGetSymbolAddress((void**)&aggx, d_aggx);
    cudaGetSymbolAddress((void**)&h1, d_h1);
    cudaGetSymbolAddress((void**)&h2, d_h2);
    cudaGetSymbolAddress((void**)&agg2, d_agg2);

    int nblk = (n + SCAN_BS - 1) / SCAN_BS;

    // CSR build
    k_zero<<<256, 256>>>(n);
    k_deg<<<(E + 255) / 256, 256>>>(dst, E);
    k_dinv<<<(n + 255) / 256, 256>>>(n);
    k_scan1<<<nblk, SCAN_BS>>>(n);
    k_scan2<<<1, SCAN_BS>>>(nblk);
    k_scan3<<<(n + 255) / 256, 256>>>(n, E);
    k_fill<<<(E + 255) / 256, 256>>>(src, dst, E);

    // Layer 1: aggregate x, then tf32 GEMM (+bias+relu)
    k_gather<IN_DIM / 4, false><<<(n + 7) / 8, 256>>>(x, aggx, nullptr, n);
    {
        dim3 grid(HID / 128, (n + 127) / 128);
        tgemm128<0><<<grid, 256>>>(n, HID, IN_DIM, aggx, W1, b1, h1);
    }
    // Layer 2: tf32 GEMM (raw), aggregate h2 (+bias+relu fused)
    {
        dim3 grid(EMB / 128, (n + 127) / 128);
        tgemm128<1><<<grid, 256>>>(n, EMB, HID, h1, W2, nullptr, h2);
    }
    k_gather<EMB / 4, true><<<(n + 7) / 8, 256>>>(h2, agg2, b2, n);

    // Heads
    k_colmean<<<256, 256>>>(agg2, n);
    k_head<<<1, 256>>>(fc1W, fc1b, fc2W, fc2b, gpW, gpb, out_global, out_value, 1.0f / (float)n);
    k_pernode<<<(n + 7) / 8, 256>>>(agg2, npW, npb, epW, out_node, n);
    k_edge<<<(E + 255) / 256, 256>>>(src, dst, epb, out_edge, E);
}